// round 1
// baseline (speedup 1.0000x reference)
#include <cuda_runtime.h>
#include <math.h>

#define Nn 4096
#define Pp 32768
#define Ee 768
#define Cc 256
#define Hh 4
#define Dd 64
#define Ll 256
#define Mm 8
#define MLPH 1024
#define NE (2*Pp)

// ---------------- scratch (static device globals; no allocations) ----------------
__device__ float g_eemb[Nn*Ee];
__device__ float g_x[Nn*Cc];
__device__ float g_A[Nn*MLPH];
__device__ float g_B[Nn*MLPH];
__device__ float g_U[Nn*MLPH];
__device__ float g_V[Nn*MLPH];
__device__ float g_h[Nn*Cc];
__device__ float g_sis[Nn*Hh], g_sid[Nn*Hh], g_ses[Nn*Hh], g_sed[Nn*Hh];
__device__ unsigned char g_m1[Pp], g_m2[Pp];
__device__ float g_loss[Pp];
__device__ int g_cnt[Nn];
__device__ int g_rp[Nn+1];
__device__ int g_cur[Nn];
__device__ int g_esrc[NE];
__device__ unsigned int g_emeta[NE];

__device__ __forceinline__ float warp_sum(float v){
#pragma unroll
    for(int o=16;o;o>>=1) v+=__shfl_xor_sync(0xffffffffu,v,o);
    return v;
}

// ---------------- CSR build ----------------
__global__ void zero_counts(){
    int i = blockIdx.x*256 + threadIdx.x;
    if(i<Nn) g_cnt[i]=0;
}

__global__ void count_edges(const int* __restrict__ pair_idx){
    int e = blockIdx.x*256 + threadIdx.x;
    if(e>=NE) return;
    int p = e & (Pp-1);
    int dst = (e<Pp) ? pair_idx[2*p+1] : pair_idx[2*p];
    atomicAdd(&g_cnt[dst],1);
}

__global__ void scan_counts(){
    __shared__ int sh[1024];
    int tid=threadIdx.x;
    int b = tid*4;
    int c0=g_cnt[b], c1=g_cnt[b+1], c2=g_cnt[b+2], c3=g_cnt[b+3];
    int tot=c0+c1+c2+c3;
    sh[tid]=tot; __syncthreads();
    for(int off=1;off<1024;off<<=1){
        int add = (tid>=off)? sh[tid-off] : 0;
        __syncthreads();
        sh[tid]+=add;
        __syncthreads();
    }
    int excl = sh[tid]-tot;
    g_rp[b]=excl;        g_cur[b]=excl;
    g_rp[b+1]=excl+c0;   g_cur[b+1]=excl+c0;
    g_rp[b+2]=excl+c0+c1; g_cur[b+2]=excl+c0+c1;
    g_rp[b+3]=excl+c0+c1+c2; g_cur[b+3]=excl+c0+c1+c2;
    if(tid==1023) g_rp[Nn]=excl+tot;
}

__global__ void scatter_edges(const int* __restrict__ pair_idx, const int* __restrict__ rel_type){
    int e = blockIdx.x*256 + threadIdx.x;
    if(e>=NE) return;
    int p = e & (Pp-1);
    int half = (e>=Pp);
    int src = half ? pair_idx[2*p+1] : pair_idx[2*p];
    int dst = half ? pair_idx[2*p]   : pair_idx[2*p+1];
    unsigned int intra = (rel_type[p]==0) ? 0x40000000u : 0u;
    int slot = atomicAdd(&g_cur[dst],1);
    g_esrc[slot]=src;
    g_emeta[slot] = (unsigned int)p | (half ? 0x80000000u : 0u) | intra;
}

// ---------------- event embedding gather-mean ----------------
__global__ void eemb_kernel(const float* __restrict__ sent_emb,
                            const int* __restrict__ ev_sent,
                            const int* __restrict__ ev_start,
                            const int* __restrict__ ev_end){
    int n = blockIdx.x;
    int tid = threadIdx.x; // 256
    int s = ev_sent[n], st = ev_start[n], en = ev_end[n];
    float inv = 1.0f/(float)(en-st);
    const float* base = sent_emb + (size_t)s*Ll*Ee;
    for(int c=tid;c<Ee;c+=256){
        float acc=0.f;
#pragma unroll
        for(int m=0;m<Mm;m++){
            int pos = st+m;
            if(pos<en){
                int pc = pos<Ll-1?pos:Ll-1;
                acc += base[(size_t)pc*Ee + c];
            }
        }
        g_eemb[(size_t)n*Ee+c]=acc*inv;
    }
}

// ---------------- SGEMM: C = A(MxK) @ B(KxN) [+bias], or UV epilogue ----------------
// mode 0: C = A@B + bias (bias optional)
// mode 1: U(=Cm) = addA + acc + b1v[col] ; Vo = addB - acc
__global__ void sgemm(const float* __restrict__ Am, const float* __restrict__ Bm,
                      const float* __restrict__ bias, float* __restrict__ Cm,
                      int M, int N, int K, int mode,
                      const float* __restrict__ addA, const float* __restrict__ addB,
                      const float* __restrict__ b1v, float* __restrict__ Vo)
{
    __shared__ float As[16][64];
    __shared__ float Bs[16][64];
    const int tid = threadIdx.x;          // 256
    const int tx = tid & 15, ty = tid >> 4;
    const int bm = blockIdx.y*64, bn = blockIdx.x*64;
    const int arow = tid >> 2;            // 0..63
    const int acol = (tid & 3) * 4;       // 0,4,8,12
    const int brow = tid >> 4;            // 0..15
    const int bcol = (tid & 15) * 4;      // 0..60
    float acc[4][4] = {};
    const float* Aptr = Am + (size_t)(bm+arow)*K + acol;
    const float* Bptr = Bm + (size_t)brow*N + bn + bcol;

    for(int k0=0;k0<K;k0+=16){
        float4 av = *(const float4*)(Aptr + k0);
        As[acol+0][arow]=av.x; As[acol+1][arow]=av.y;
        As[acol+2][arow]=av.z; As[acol+3][arow]=av.w;
        *(float4*)&Bs[brow][bcol] = *(const float4*)(Bptr + (size_t)k0*N);
        __syncthreads();
#pragma unroll
        for(int k=0;k<16;k++){
            float4 a = *(const float4*)&As[k][ty*4];
            float4 b = *(const float4*)&Bs[k][tx*4];
            acc[0][0]+=a.x*b.x; acc[0][1]+=a.x*b.y; acc[0][2]+=a.x*b.z; acc[0][3]+=a.x*b.w;
            acc[1][0]+=a.y*b.x; acc[1][1]+=a.y*b.y; acc[1][2]+=a.y*b.z; acc[1][3]+=a.y*b.w;
            acc[2][0]+=a.z*b.x; acc[2][1]+=a.z*b.y; acc[2][2]+=a.z*b.z; acc[2][3]+=a.z*b.w;
            acc[3][0]+=a.w*b.x; acc[3][1]+=a.w*b.y; acc[3][2]+=a.w*b.z; acc[3][3]+=a.w*b.w;
        }
        __syncthreads();
    }

    if(mode==0){
#pragma unroll
        for(int i=0;i<4;i++){
            int row = bm + ty*4 + i;
#pragma unroll
            for(int j=0;j<4;j++){
                int col = bn + tx*4 + j;
                float v = acc[i][j];
                if(bias) v += bias[col];
                Cm[(size_t)row*N+col]=v;
            }
        }
    } else {
#pragma unroll
        for(int i=0;i<4;i++){
            int row = bm + ty*4 + i;
#pragma unroll
            for(int j=0;j<4;j++){
                int col = bn + tx*4 + j;
                size_t idx = (size_t)row*N+col;
                float g = acc[i][j];
                Cm[idx] = addA[idx] + g + b1v[col];
                Vo[idx] = addB[idx] - g;
            }
        }
    }
}

// ---------------- pair MLP + softmax + loss + masks ----------------
__global__ void pair_kernel(const int* __restrict__ pair_idx,
                            const float* __restrict__ W2, const float* __restrict__ b2,
                            const int* __restrict__ target,
                            float w_it, int accum, float* __restrict__ pred_out)
{
    __shared__ float W2s[3072];
    __shared__ float b2s[3];
    int tid = threadIdx.x; // 256
    for(int i=tid;i<3072;i+=256) W2s[i]=W2[i];
    if(tid<3) b2s[tid]=b2[tid];
    __syncthreads();
    int p = blockIdx.x*8 + (tid>>5);
    int lane = tid & 31;
    int p0 = pair_idx[2*p], p1 = pair_idx[2*p+1];
    const float* ur = g_U + (size_t)p0*MLPH;
    const float* vr = g_V + (size_t)p1*MLPH;
    float a0=0.f,a1=0.f,a2=0.f;
#pragma unroll 4
    for(int j=lane;j<MLPH;j+=32){
        float hv = ur[j]+vr[j];
        hv = fmaxf(hv,0.f);
        a0 += hv*W2s[j*3+0];
        a1 += hv*W2s[j*3+1];
        a2 += hv*W2s[j*3+2];
    }
    a0=warp_sum(a0); a1=warp_sum(a1); a2=warp_sum(a2);
    if(lane==0){
        float r0=a0+b2s[0], r1=a1+b2s[1], r2=a2+b2s[2];
        float mv=r0; int arg=0;
        if(r1>mv){mv=r1;arg=1;}
        if(r2>mv){mv=r2;arg=2;}
        float e0=expf(r0-mv), e1=expf(r1-mv), e2=expf(r2-mv);
        float ssum=e0+e1+e2;
        int conf = (1.0f/ssum) > 0.5f;   // psoft.max = exp(0)/sum
        g_m1[p] = (unsigned char)(conf && (arg==1));
        g_m2[p] = (unsigned char)(conf && (arg==2));
        int t = target[p];
        float lse = mv + logf(ssum);
        float pr = (t==0)?r0:((t==1)?r1:r2);
        float prev = accum ? g_loss[p] : 0.f;
        g_loss[p] = prev + w_it*(lse - pr);
        if(pred_out){
            pred_out[3*p+0]=r0; pred_out[3*p+1]=r1; pred_out[3*p+2]=r2;
        }
    }
}

__global__ void loss_reduce(float* __restrict__ out){
    __shared__ float sh[256];
    int tid = threadIdx.x;
    float s=0.f;
    for(int i=tid;i<Pp;i+=256) s+=g_loss[i];
    sh[tid]=s; __syncthreads();
    for(int o=128;o;o>>=1){
        if(tid<o) sh[tid]+=sh[tid+o];
        __syncthreads();
    }
    if(tid==0) out[0]=sh[0]/(float)Pp;
}

// ---------------- per-node attention score precompute ----------------
__global__ void s_kernel(const float* __restrict__ asi, const float* __restrict__ adi,
                         const float* __restrict__ ase, const float* __restrict__ ade){
    int n = blockIdx.x;
    int w = threadIdx.x>>5, lane = threadIdx.x&31;  // 128 threads, warp per head
    const float* hr = g_h + (size_t)n*Cc + w*Dd;
    float h0 = hr[lane], h1 = hr[32+lane];
    float v0 = h0*asi[w*Dd+lane] + h1*asi[w*Dd+32+lane];
    float v1 = h0*adi[w*Dd+lane] + h1*adi[w*Dd+32+lane];
    float v2 = h0*ase[w*Dd+lane] + h1*ase[w*Dd+32+lane];
    float v3 = h0*ade[w*Dd+lane] + h1*ade[w*Dd+32+lane];
    v0=warp_sum(v0); v1=warp_sum(v1); v2=warp_sum(v2); v3=warp_sum(v3);
    if(lane==0){
        g_sis[n*Hh+w]=v0; g_sid[n*Hh+w]=v1;
        g_ses[n*Hh+w]=v2; g_sed[n*Hh+w]=v3;
    }
}

// ---------------- fused intra+inter GAT attention, writes x ----------------
__global__ void attn_kernel(){
    int n = blockIdx.x;
    int tid = threadIdx.x; // 256
    int hh = tid>>6;       // head
    __shared__ int ssrc[64];
    __shared__ unsigned int smeta[64];
    __shared__ float exI[64][4];
    __shared__ float exE[64][4];
    __shared__ float shmaxI[4], shmaxE[4], shdenI[4], shdenE[4];
    __shared__ float wred[8][8];

    float sdI[4], sdE[4], aself[4];
#pragma unroll
    for(int h=0;h<4;h++){
        sdI[h]=g_sid[n*4+h];
        sdE[h]=g_sed[n*4+h];
        float a = g_sis[n*4+h]+sdI[h];
        aself[h] = (a>=0.f)? a : 0.2f*a;
    }

    int beg = g_rp[n], end = g_rp[n+1];

    // -------- pass 1: per-head maxima --------
    float mI[4], mE[4];
#pragma unroll
    for(int h=0;h<4;h++){ mI[h]=fmaxf(-1e9f,aself[h]); mE[h]=-1e9f; }
    for(int e=beg+tid;e<end;e+=256){
        int src = g_esrc[e];
        unsigned int meta = g_emeta[e];
        unsigned int p = meta & 0x0FFFFFFFu;
        bool mm = (meta & 0x80000000u) ? (g_m2[p]!=0) : (g_m1[p]!=0);
        if(!mm) continue;
        if(meta & 0x40000000u){
#pragma unroll
            for(int h=0;h<4;h++){
                float a = g_sis[src*4+h]+sdI[h];
                a = (a>=0.f)? a : 0.2f*a;
                mI[h]=fmaxf(mI[h],a);
            }
        } else {
#pragma unroll
            for(int h=0;h<4;h++){
                float a = g_ses[src*4+h]+sdE[h];
                a = (a>=0.f)? a : 0.2f*a;
                mE[h]=fmaxf(mE[h],a);
            }
        }
    }
#pragma unroll
    for(int o=16;o;o>>=1){
#pragma unroll
        for(int h=0;h<4;h++){
            mI[h]=fmaxf(mI[h],__shfl_xor_sync(0xffffffffu,mI[h],o));
            mE[h]=fmaxf(mE[h],__shfl_xor_sync(0xffffffffu,mE[h],o));
        }
    }
    int wid = tid>>5, lane = tid&31;
    if(lane==0){
#pragma unroll
        for(int h=0;h<4;h++){ wred[wid][h]=mI[h]; wred[wid][4+h]=mE[h]; }
    }
    __syncthreads();
    if(tid<8){
        float m=-1e9f;
#pragma unroll
        for(int w=0;w<8;w++) m=fmaxf(m,wred[w][tid]);
        if(tid<4) shmaxI[tid]=m; else shmaxE[tid-4]=m;
    }
    __syncthreads();
    float mymaxI = shmaxI[hh];
    float mymaxE = shmaxE[hh];

    // -------- pass 2: exp weights + weighted accumulation (chunks of 64 edges) --------
    float accI=0.f, accE=0.f, dI=0.f, dE=0.f;
    for(int c0=beg;c0<end;c0+=64){
        int ne = min(64, end-c0);
        if(tid<ne){ ssrc[tid]=g_esrc[c0+tid]; smeta[tid]=g_emeta[c0+tid]; }
        __syncthreads();
        int i = tid & 63;
        if(i<ne){
            int src = ssrc[i];
            unsigned int meta = smeta[i];
            unsigned int p = meta & 0x0FFFFFFFu;
            bool mm = (meta & 0x80000000u) ? (g_m2[p]!=0) : (g_m1[p]!=0);
            float eI=0.f, eE=0.f;
            if(mm){
                if(meta & 0x40000000u){
                    float a = g_sis[src*4+hh]+sdI[hh];
                    a = (a>=0.f)? a : 0.2f*a;
                    eI = expf(a - mymaxI);
                } else {
                    float a = g_ses[src*4+hh]+sdE[hh];
                    a = (a>=0.f)? a : 0.2f*a;
                    eE = expf(a - mymaxE);
                }
            }
            exI[i][hh]=eI; exE[i][hh]=eE;
            dI += eI; dE += eE;
        }
        __syncthreads();
        for(int i2=0;i2<ne;i2++){
            float wI = exI[i2][hh];
            float wE = exE[i2][hh];
            if(wI!=0.f || wE!=0.f){
                float hv = g_h[(size_t)ssrc[i2]*Cc + tid];
                accI += wI*hv;
                accE += wE*hv;
            }
        }
        __syncthreads();
    }

    // -------- denominator reduction (per head across 64 edge-slots = 2 warps) --------
    float rdI = warp_sum(dI), rdE = warp_sum(dE);
    if(lane==0){ wred[wid][0]=rdI; wred[wid][1]=rdE; }
    __syncthreads();
    if(tid<4){
        float selfe = expf(aself[tid]-shmaxI[tid]);
        shdenI[tid] = wred[2*tid][0]+wred[2*tid+1][0]+selfe;
        shdenE[tid] = wred[2*tid][1]+wred[2*tid+1][1];
    }
    __syncthreads();

    float selfe = expf(aself[hh]-mymaxI);
    accI += selfe * g_h[(size_t)n*Cc + tid];

    float outI = accI/(shdenI[hh]+1e-9f);
    float outE = accE/(shdenE[hh]+1e-9f);
    g_x[(size_t)n*Cc + tid] = 0.5f*outI + 0.5f*outE;
}

// ---------------- host launch ----------------
extern "C" void kernel_launch(void* const* d_in, const int* in_sizes, int n_in,
                              void* d_out, int out_size)
{
    const float* sent_emb  = (const float*)d_in[0];
    const float* proj_in_W = (const float*)d_in[1];
    const float* proj_in_b = (const float*)d_in[2];
    const float* proj_W    = (const float*)d_in[3];
    const float* proj_b    = (const float*)d_in[4];
    const float* asi       = (const float*)d_in[5];
    const float* adi       = (const float*)d_in[6];
    const float* ase       = (const float*)d_in[7];
    const float* ade       = (const float*)d_in[8];
    const float* mlp_W1    = (const float*)d_in[9];
    const float* mlp_b1    = (const float*)d_in[10];
    const float* mlp_W2    = (const float*)d_in[11];
    const float* mlp_b2    = (const float*)d_in[12];
    const int*   ev_sent   = (const int*)d_in[13];
    const int*   ev_start  = (const int*)d_in[14];
    const int*   ev_end    = (const int*)d_in[15];
    const int*   pair_idx  = (const int*)d_in[16];
    const int*   rel_type  = (const int*)d_in[17];
    const int*   target    = (const int*)d_in[18];
    float* out = (float*)d_out;

    static float *pE=nullptr,*pX=nullptr,*pA=nullptr,*pB=nullptr,*pU=nullptr,*pV=nullptr,*pH=nullptr;
    if(!pE){
        cudaGetSymbolAddress((void**)&pE, g_eemb);
        cudaGetSymbolAddress((void**)&pX, g_x);
        cudaGetSymbolAddress((void**)&pA, g_A);
        cudaGetSymbolAddress((void**)&pB, g_B);
        cudaGetSymbolAddress((void**)&pU, g_U);
        cudaGetSymbolAddress((void**)&pV, g_V);
        cudaGetSymbolAddress((void**)&pH, g_h);
    }

    // CSR build (fixed topology; rebuilt each call for determinism of the captured graph)
    zero_counts<<<(Nn+255)/256,256>>>();
    count_edges<<<NE/256,256>>>(pair_idx);
    scan_counts<<<1,1024>>>();
    scatter_edges<<<NE/256,256>>>(pair_idx, rel_type);

    // event embeddings, initial projection, iteration-invariant A/B
    eemb_kernel<<<Nn,256>>>(sent_emb, ev_sent, ev_start, ev_end);
    sgemm<<<dim3(Cc/64, Nn/64),256>>>(pE, proj_in_W, proj_in_b, pX,
                                      Nn, Cc, Ee, 0, nullptr,nullptr,nullptr,nullptr);
    sgemm<<<dim3(MLPH/64, Nn/64),256>>>(pE, mlp_W1, nullptr, pA,
                                        Nn, MLPH, Ee, 0, nullptr,nullptr,nullptr,nullptr);
    sgemm<<<dim3(MLPH/64, Nn/64),256>>>(pE, mlp_W1 + (size_t)Ee*MLPH, nullptr, pB,
                                        Nn, MLPH, Ee, 0, nullptr,nullptr,nullptr,nullptr);

    for(int it=0; it<3; it++){
        // U = A + x@W1d + b1 ; V = B - x@W1d
        sgemm<<<dim3(MLPH/64, Nn/64),256>>>(pX, mlp_W1 + (size_t)2*Ee*MLPH, nullptr, pU,
                                            Nn, MLPH, Cc, 1, pA, pB, mlp_b1, pV);
        pair_kernel<<<Pp/8,256>>>(pair_idx, mlp_W2, mlp_b2, target,
                                  1.0f/(float)(it+1), it>0,
                                  (it==2) ? (out+1) : nullptr);
        if(it<2){
            sgemm<<<dim3(Cc/64, Nn/64),256>>>(pX, proj_W, proj_b, pH,
                                              Nn, Cc, Cc, 0, nullptr,nullptr,nullptr,nullptr);
            s_kernel<<<Nn,128>>>(asi, adi, ase, ade);
            attn_kernel<<<Nn,256>>>();
        }
    }
    loss_reduce<<<1,256>>>(out);
}

// round 3
// speedup vs baseline: 1.6339x; 1.6339x over previous
#include <cuda_runtime.h>
#include <cuda_bf16.h>
#include <math.h>
#include <stdint.h>

#define Nn 4096
#define Pp 32768
#define Ee 768
#define Cc 256
#define Hh 4
#define Dd 64
#define Ll 256
#define Mm 8
#define MLPH 1024
#define NE (2*Pp)

// K chunks: K=768 -> 12 base chunks of 64 bf16; K=256 -> 4
#define KC_E 12
#define KC_C 4

// ---------------- scratch ----------------
__device__ float g_eemb[Nn*Ee];
__device__ float g_x[Nn*Cc];
__device__ float g_A[Nn*MLPH];
__device__ float g_B[Nn*MLPH];
__device__ float g_U[Nn*MLPH];
__device__ float g_V[Nn*MLPH];
__device__ float g_h[Nn*Cc];
__device__ float g_sis[Nn*Hh], g_sid[Nn*Hh], g_ses[Nn*Hh], g_sed[Nn*Hh];
__device__ unsigned char g_m1[Pp], g_m2[Pp];
__device__ float g_loss[Pp];
__device__ int g_cnt[Nn];
__device__ int g_rp[Nn+1];
__device__ int g_cur[Nn];
__device__ int g_esrc[NE];
__device__ unsigned int g_emeta[NE];

// bf16 pre-swizzled panels (tile = 128 rows x 64 bf16 = 8192 elems = 16KB)
__device__ __nv_bfloat16 g_PE  [(size_t)32*(2*KC_E)*8192]; // e_emb hi|lo
__device__ __nv_bfloat16 g_PX  [(size_t)32*(2*KC_C)*8192]; // x hi|lo
__device__ __nv_bfloat16 g_PWin[(size_t)2 *(2*KC_E)*8192];
__device__ __nv_bfloat16 g_PW1a[(size_t)8 *(2*KC_E)*8192];
__device__ __nv_bfloat16 g_PW1b[(size_t)8 *(2*KC_E)*8192];
__device__ __nv_bfloat16 g_PW1d[(size_t)8 *(2*KC_C)*8192];
__device__ __nv_bfloat16 g_PPrj[(size_t)2 *(2*KC_C)*8192];

__device__ __forceinline__ float warp_sum(float v){
#pragma unroll
    for(int o=16;o;o>>=1) v+=__shfl_xor_sync(0xffffffffu,v,o);
    return v;
}

// ---------------- PTX helpers (sm_80-era: ldmatrix / mma.sync / cp.async) ----------------
__device__ __forceinline__ uint32_t smem_to_u32(const void* p){
    uint32_t a;
    asm("{ .reg .u64 t; cvta.to.shared.u64 t, %1; cvt.u32.u64 %0, t; }" : "=r"(a) : "l"(p));
    return a;
}
__device__ __forceinline__ void ldmx4(uint32_t &r0,uint32_t &r1,uint32_t &r2,uint32_t &r3,uint32_t addr){
    asm volatile("ldmatrix.sync.aligned.m8n8.x4.shared.b16 {%0,%1,%2,%3}, [%4];"
        : "=r"(r0),"=r"(r1),"=r"(r2),"=r"(r3) : "r"(addr));
}
__device__ __forceinline__ void mma16816(float* c, const uint32_t* a, uint32_t b0, uint32_t b1){
    asm volatile("mma.sync.aligned.m16n8k16.row.col.f32.bf16.bf16.f32 "
        "{%0,%1,%2,%3}, {%4,%5,%6,%7}, {%8,%9}, {%0,%1,%2,%3};"
        : "+f"(c[0]),"+f"(c[1]),"+f"(c[2]),"+f"(c[3])
        : "r"(a[0]),"r"(a[1]),"r"(a[2]),"r"(a[3]),"r"(b0),"r"(b1));
}
#define CP_ASYNC16(dst,src) \
    asm volatile("cp.async.cg.shared.global [%0], [%1], 16;" :: "r"(dst),"l"(src))
#define CP_COMMIT asm volatile("cp.async.commit_group;" ::: "memory")
#define CP_WAIT1  asm volatile("cp.async.wait_group 1;" ::: "memory")
#define CP_WAIT0  asm volatile("cp.async.wait_group 0;" ::: "memory")

__device__ __forceinline__ uint32_t sw128(uint32_t off){ return off ^ ((off>>3)&0x70u); }

// ---------------- CSR build ----------------
__global__ void zero_counts(){
    int i = blockIdx.x*256 + threadIdx.x;
    if(i<Nn) g_cnt[i]=0;
}
__global__ void count_edges(const int* __restrict__ pair_idx){
    int e = blockIdx.x*256 + threadIdx.x;
    if(e>=NE) return;
    int p = e & (Pp-1);
    int dst = (e<Pp) ? pair_idx[2*p+1] : pair_idx[2*p];
    atomicAdd(&g_cnt[dst],1);
}
__global__ void scan_counts(){
    __shared__ int sh[1024];
    int tid=threadIdx.x;
    int b = tid*4;
    int c0=g_cnt[b], c1=g_cnt[b+1], c2=g_cnt[b+2], c3=g_cnt[b+3];
    int tot=c0+c1+c2+c3;
    sh[tid]=tot; __syncthreads();
    for(int off=1;off<1024;off<<=1){
        int add = (tid>=off)? sh[tid-off] : 0;
        __syncthreads();
        sh[tid]+=add;
        __syncthreads();
    }
    int excl = sh[tid]-tot;
    g_rp[b]=excl;            g_cur[b]=excl;
    g_rp[b+1]=excl+c0;       g_cur[b+1]=excl+c0;
    g_rp[b+2]=excl+c0+c1;    g_cur[b+2]=excl+c0+c1;
    g_rp[b+3]=excl+c0+c1+c2; g_cur[b+3]=excl+c0+c1+c2;
    if(tid==1023) g_rp[Nn]=excl+tot;
}
__global__ void scatter_edges(const int* __restrict__ pair_idx, const int* __restrict__ rel_type){
    int e = blockIdx.x*256 + threadIdx.x;
    if(e>=NE) return;
    int p = e & (Pp-1);
    int half = (e>=Pp);
    int src = half ? pair_idx[2*p+1] : pair_idx[2*p];
    int dst = half ? pair_idx[2*p]   : pair_idx[2*p+1];
    unsigned int intra = (rel_type[p]==0) ? 0x40000000u : 0u;
    int slot = atomicAdd(&g_cur[dst],1);
    g_esrc[slot]=src;
    g_emeta[slot] = (unsigned int)p | (half ? 0x80000000u : 0u) | intra;
}

// ---------------- event embedding gather-mean ----------------
__global__ void eemb_kernel(const float* __restrict__ sent_emb,
                            const int* __restrict__ ev_sent,
                            const int* __restrict__ ev_start,
                            const int* __restrict__ ev_end){
    int n = blockIdx.x;
    int tid = threadIdx.x; // 256
    int s = ev_sent[n], st = ev_start[n], en = ev_end[n];
    float inv = 1.0f/(float)(en-st);
    const float* base = sent_emb + (size_t)s*Ll*Ee;
    for(int c=tid;c<Ee;c+=256){
        float acc=0.f;
#pragma unroll
        for(int m=0;m<Mm;m++){
            int pos = st+m;
            if(pos<en){
                int pc = pos<Ll-1?pos:Ll-1;
                acc += base[(size_t)pc*Ee + c];
            }
        }
        g_eemb[(size_t)n*Ee+c]=acc*inv;
    }
}

// ---------------- panel prep: fp32 -> bf16 hi/lo, pre-swizzled tile images ----------------
__global__ void prep_act(const float* __restrict__ X, __nv_bfloat16* __restrict__ P, int K, int KcN){
    int idx = blockIdx.x*256 + threadIdx.x;
    int m = idx / K, k = idx - m*K;
    float v = X[idx];
    __nv_bfloat16 hi = __float2bfloat16(v);
    __nv_bfloat16 lo = __float2bfloat16(v - __bfloat162float(hi));
    int mblk = m>>7, row = m&127, chunk = k>>6, col = k&63;
    uint32_t off = sw128((uint32_t)(row*128 + col*2));
    char* baseHi = (char*)(P + ((size_t)mblk*(2*KcN)+chunk)*8192);
    char* baseLo = (char*)(P + ((size_t)mblk*(2*KcN)+KcN+chunk)*8192);
    *(__nv_bfloat16*)(baseHi + off) = hi;
    *(__nv_bfloat16*)(baseLo + off) = lo;
}
__global__ void prep_w(const float* __restrict__ W, __nv_bfloat16* __restrict__ P, int N, int KcN){
    int idx = blockIdx.x*256 + threadIdx.x;
    int k = idx / N, n = idx - k*N;
    float v = W[idx];
    __nv_bfloat16 hi = __float2bfloat16(v);
    __nv_bfloat16 lo = __float2bfloat16(v - __bfloat162float(hi));
    int nblk = n>>7, row = n&127, chunk = k>>6, col = k&63;
    uint32_t off = sw128((uint32_t)(row*128 + col*2));
    char* baseHi = (char*)(P + ((size_t)nblk*(2*KcN)+chunk)*8192);
    char* baseLo = (char*)(P + ((size_t)nblk*(2*KcN)+KcN+chunk)*8192);
    *(__nv_bfloat16*)(baseHi + off) = hi;
    *(__nv_bfloat16*)(baseLo + off) = lo;
}

// ---------------- mma.sync bf16-split GEMM ----------------
// D[M,N] = X @ W via 3 segments: Ah*Bh + Al*Bh + Ah*Bl (K extended 3x).
// mode 0: Cout = D (+bias).  mode 1: Cout(U) = addA + D + bias; Vout = addB - D.
// CTA tile 128x128, 8 warps (warp tile 32m x 64n), cp.async double buffer.
__global__ void __launch_bounds__(256)
gemm_bf16(const __nv_bfloat16* __restrict__ Apan,
          const __nv_bfloat16* __restrict__ Bpan,
          int KcN, int mode,
          const float* __restrict__ bias,
          float* __restrict__ Cout,
          const float* __restrict__ addA,
          const float* __restrict__ addB,
          float* __restrict__ Vout,
          int N)
{
    extern __shared__ __align__(128) char smem[];
    const uint32_t sb = smem_to_u32(smem);
    const int tid = threadIdx.x;
    const int wid = tid >> 5;
    const int lane = tid & 31;
    const int mblk = blockIdx.y, nblk = blockIdx.x;
    const int wm = wid & 3;        // m quadrant (32 rows)
    const int wn = wid >> 2;       // n half (64 cols)
    const int nc = 3*KcN;

    float acc[2][8][4];
#pragma unroll
    for(int i=0;i<2;i++)
#pragma unroll
        for(int j=0;j<8;j++)
#pragma unroll
            for(int q=0;q<4;q++) acc[i][j][q]=0.f;

    // per-thread ldmatrix address components
    const int arow = wm*32 + (lane & 15);
    const int acol = ((lane >> 4) & 1) * 8;              // bf16 col within k16
    const int bnof = ((lane >> 4) & 1) * 8 + (lane & 7); // n row within n16 group
    const int bkof = ((lane >> 3) & 1) * 8;              // bf16 col within k16

    // chunk loader: linear 16B copy of pre-swizzled 16KB tiles
    auto chunk_src = [&](int c, const uint4*& Ag, const uint4*& Bg){
        int seg = (c >= 2*KcN) ? 2 : ((c >= KcN) ? 1 : 0);
        int within = c - seg*KcN;
        int aC = (seg==1 ? KcN : 0) + within;
        int bC = (seg==2 ? KcN : 0) + within;
        Ag = (const uint4*)(Apan + ((size_t)mblk*(2*KcN)+aC)*8192);
        Bg = (const uint4*)(Bpan + ((size_t)nblk*(2*KcN)+bC)*8192);
    };

    {   // preload chunk 0
        const uint4 *Ag, *Bg;
        chunk_src(0, Ag, Bg);
#pragma unroll
        for(int i=0;i<4;i++){
            CP_ASYNC16(sb + (tid + i*256)*16, Ag + tid + i*256);
            CP_ASYNC16(sb + 16384 + (tid + i*256)*16, Bg + tid + i*256);
        }
        CP_COMMIT;
    }

    for(int c=0;c<nc;c++){
        int buf = c & 1;
        if(c+1 < nc){
            const uint4 *Ag, *Bg;
            chunk_src(c+1, Ag, Bg);
            uint32_t db = sb + ((c+1)&1)*32768;
#pragma unroll
            for(int i=0;i<4;i++){
                CP_ASYNC16(db + (tid + i*256)*16, Ag + tid + i*256);
                CP_ASYNC16(db + 16384 + (tid + i*256)*16, Bg + tid + i*256);
            }
            CP_COMMIT;
            CP_WAIT1;
        } else {
            CP_WAIT0;
        }
        __syncthreads();

        uint32_t abase = sb + buf*32768;
        uint32_t bbase = abase + 16384;
#pragma unroll
        for(int ks=0;ks<4;ks++){
            uint32_t af[2][4];
#pragma unroll
            for(int mf=0;mf<2;mf++){
                uint32_t off = (uint32_t)((arow + mf*16)*128 + (ks*16 + acol)*2);
                ldmx4(af[mf][0],af[mf][1],af[mf][2],af[mf][3], abase + sw128(off));
            }
#pragma unroll
            for(int g=0;g<4;g++){
                uint32_t b0,b1,b2,b3;
                uint32_t off = (uint32_t)((wn*64 + g*16 + bnof)*128 + (ks*16 + bkof)*2);
                ldmx4(b0,b1,b2,b3, bbase + sw128(off));
#pragma unroll
                for(int mf=0;mf<2;mf++){
                    mma16816(acc[mf][2*g+0], af[mf], b0, b1);
                    mma16816(acc[mf][2*g+1], af[mf], b2, b3);
                }
            }
        }
        __syncthreads();
    }

    // epilogue: thread (mf,nf) -> rows r, r+8 ; cols cc, cc+1
    int rbase = mblk*128 + wm*32 + (lane>>2);
    int cbase = nblk*128 + wn*64 + (lane&3)*2;
#pragma unroll
    for(int mf=0;mf<2;mf++){
#pragma unroll
        for(int nf=0;nf<8;nf++){
            int r  = rbase + mf*16;
            int cc = cbase + nf*8;
            size_t i0 = (size_t)r*N + cc;
            size_t i1 = (size_t)(r+8)*N + cc;
            float g0=acc[mf][nf][0], g1=acc[mf][nf][1];
            float g2=acc[mf][nf][2], g3=acc[mf][nf][3];
            if(mode==0){
                float b0 = bias ? bias[cc]   : 0.f;
                float b1 = bias ? bias[cc+1] : 0.f;
                *(float2*)(Cout + i0) = make_float2(g0+b0, g1+b1);
                *(float2*)(Cout + i1) = make_float2(g2+b0, g3+b1);
            } else {
                float b0 = bias[cc], b1 = bias[cc+1];
                float2 a0 = *(const float2*)(addA + i0);
                float2 a1 = *(const float2*)(addA + i1);
                float2 v0 = *(const float2*)(addB + i0);
                float2 v1 = *(const float2*)(addB + i1);
                *(float2*)(Cout + i0) = make_float2(a0.x+g0+b0, a0.y+g1+b1);
                *(float2*)(Cout + i1) = make_float2(a1.x+g2+b0, a1.y+g3+b1);
                *(float2*)(Vout + i0) = make_float2(v0.x-g0, v0.y-g1);
                *(float2*)(Vout + i1) = make_float2(v1.x-g2, v1.y-g3);
            }
        }
    }
}

// ---------------- pair MLP + softmax + loss + masks ----------------
__global__ void pair_kernel(const int* __restrict__ pair_idx,
                            const float* __restrict__ W2, const float* __restrict__ b2,
                            const int* __restrict__ target,
                            float w_it, int accum, float* __restrict__ pred_out)
{
    __shared__ float W2s[3072];
    __shared__ float b2s[3];
    int tid = threadIdx.x; // 256
    for(int i=tid;i<3072;i+=256) W2s[i]=W2[i];
    if(tid<3) b2s[tid]=b2[tid];
    __syncthreads();
    int p = blockIdx.x*8 + (tid>>5);
    int lane = tid & 31;
    int p0 = pair_idx[2*p], p1 = pair_idx[2*p+1];
    const float* ur = g_U + (size_t)p0*MLPH;
    const float* vr = g_V + (size_t)p1*MLPH;
    float a0=0.f,a1=0.f,a2=0.f;
#pragma unroll 4
    for(int j=lane;j<MLPH;j+=32){
        float hv = ur[j]+vr[j];
        hv = fmaxf(hv,0.f);
        a0 += hv*W2s[j*3+0];
        a1 += hv*W2s[j*3+1];
        a2 += hv*W2s[j*3+2];
    }
    a0=warp_sum(a0); a1=warp_sum(a1); a2=warp_sum(a2);
    if(lane==0){
        float r0=a0+b2s[0], r1=a1+b2s[1], r2=a2+b2s[2];
        float mv=r0; int arg=0;
        if(r1>mv){mv=r1;arg=1;}
        if(r2>mv){mv=r2;arg=2;}
        float e0=expf(r0-mv), e1=expf(r1-mv), e2=expf(r2-mv);
        float ssum=e0+e1+e2;
        int conf = (1.0f/ssum) > 0.5f;
        g_m1[p] = (unsigned char)(conf && (arg==1));
        g_m2[p] = (unsigned char)(conf && (arg==2));
        int t = target[p];
        float lse = mv + logf(ssum);
        float pr = (t==0)?r0:((t==1)?r1:r2);
        float prev = accum ? g_loss[p] : 0.f;
        g_loss[p] = prev + w_it*(lse - pr);
        if(pred_out){
            pred_out[3*p+0]=r0; pred_out[3*p+1]=r1; pred_out[3*p+2]=r2;
        }
    }
}

__global__ void loss_reduce(float* __restrict__ out){
    __shared__ float sh[256];
    int tid = threadIdx.x;
    float s=0.f;
    for(int i=tid;i<Pp;i+=256) s+=g_loss[i];
    sh[tid]=s; __syncthreads();
    for(int o=128;o;o>>=1){
        if(tid<o) sh[tid]+=sh[tid+o];
        __syncthreads();
    }
    if(tid==0) out[0]=sh[0]/(float)Pp;
}

// ---------------- per-node attention score precompute ----------------
__global__ void s_kernel(const float* __restrict__ asi, const float* __restrict__ adi,
                         const float* __restrict__ ase, const float* __restrict__ ade){
    int n = blockIdx.x;
    int w = threadIdx.x>>5, lane = threadIdx.x&31;
    const float* hr = g_h + (size_t)n*Cc + w*Dd;
    float h0 = hr[lane], h1 = hr[32+lane];
    float v0 = h0*asi[w*Dd+lane] + h1*asi[w*Dd+32+lane];
    float v1 = h0*adi[w*Dd+lane] + h1*adi[w*Dd+32+lane];
    float v2 = h0*ase[w*Dd+lane] + h1*ase[w*Dd+32+lane];
    float v3 = h0*ade[w*Dd+lane] + h1*ade[w*Dd+32+lane];
    v0=warp_sum(v0); v1=warp_sum(v1); v2=warp_sum(v2); v3=warp_sum(v3);
    if(lane==0){
        g_sis[n*Hh+w]=v0; g_sid[n*Hh+w]=v1;
        g_ses[n*Hh+w]=v2; g_sed[n*Hh+w]=v3;
    }
}

// ---------------- fused intra+inter GAT attention, writes x ----------------
__global__ void attn_kernel(){
    int n = blockIdx.x;
    int tid = threadIdx.x; // 256
    int hh = tid>>6;
    __shared__ int ssrc[64];
    __shared__ unsigned int smeta[64];
    __shared__ float exI[64][4];
    __shared__ float exE[64][4];
    __shared__ float shmaxI[4], shmaxE[4], shdenI[4], shdenE[4];
    __shared__ float wred[8][8];

    float sdI[4], sdE[4], aself[4];
#pragma unroll
    for(int h=0;h<4;h++){
        sdI[h]=g_sid[n*4+h];
        sdE[h]=g_sed[n*4+h];
        float a = g_sis[n*4+h]+sdI[h];
        aself[h] = (a>=0.f)? a : 0.2f*a;
    }

    int beg = g_rp[n], end = g_rp[n+1];

    float mI[4], mE[4];
#pragma unroll
    for(int h=0;h<4;h++){ mI[h]=fmaxf(-1e9f,aself[h]); mE[h]=-1e9f; }
    for(int e=beg+tid;e<end;e+=256){
        int src = g_esrc[e];
        unsigned int meta = g_emeta[e];
        unsigned int p = meta & 0x0FFFFFFFu;
        bool mm = (meta & 0x80000000u) ? (g_m2[p]!=0) : (g_m1[p]!=0);
        if(!mm) continue;
        if(meta & 0x40000000u){
#pragma unroll
            for(int h=0;h<4;h++){
                float a = g_sis[src*4+h]+sdI[h];
                a = (a>=0.f)? a : 0.2f*a;
                mI[h]=fmaxf(mI[h],a);
            }
        } else {
#pragma unroll
            for(int h=0;h<4;h++){
                float a = g_ses[src*4+h]+sdE[h];
                a = (a>=0.f)? a : 0.2f*a;
                mE[h]=fmaxf(mE[h],a);
            }
        }
    }
#pragma unroll
    for(int o=16;o;o>>=1){
#pragma unroll
        for(int h=0;h<4;h++){
            mI[h]=fmaxf(mI[h],__shfl_xor_sync(0xffffffffu,mI[h],o));
            mE[h]=fmaxf(mE[h],__shfl_xor_sync(0xffffffffu,mE[h],o));
        }
    }
    int wid = tid>>5, lane = tid&31;
    if(lane==0){
#pragma unroll
        for(int h=0;h<4;h++){ wred[wid][h]=mI[h]; wred[wid][4+h]=mE[h]; }
    }
    __syncthreads();
    if(tid<8){
        float m=-1e9f;
#pragma unroll
        for(int w=0;w<8;w++) m=fmaxf(m,wred[w][tid]);
        if(tid<4) shmaxI[tid]=m; else shmaxE[tid-4]=m;
    }
    __syncthreads();
    float mymaxI = shmaxI[hh];
    float mymaxE = shmaxE[hh];

    float accI=0.f, accE=0.f, dI=0.f, dE=0.f;
    for(int c0=beg;c0<end;c0+=64){
        int ne = min(64, end-c0);
        if(tid<ne){ ssrc[tid]=g_esrc[c0+tid]; smeta[tid]=g_emeta[c0+tid]; }
        __syncthreads();
        int i = tid & 63;
        if(i<ne){
            int src = ssrc[i];
            unsigned int meta = smeta[i];
            unsigned int p = meta & 0x0FFFFFFFu;
            bool mm = (meta & 0x80000000u) ? (g_m2[p]!=0) : (g_m1[p]!=0);
            float eI=0.f, eE=0.f;
            if(mm){
                if(meta & 0x40000000u){
                    float a = g_sis[src*4+hh]+sdI[hh];
                    a = (a>=0.f)? a : 0.2f*a;
                    eI = expf(a - mymaxI);
                } else {
                    float a = g_ses[src*4+hh]+sdE[hh];
                    a = (a>=0.f)? a : 0.2f*a;
                    eE = expf(a - mymaxE);
                }
            }
            exI[i][hh]=eI; exE[i][hh]=eE;
            dI += eI; dE += eE;
        }
        __syncthreads();
        for(int i2=0;i2<ne;i2++){
            float wI = exI[i2][hh];
            float wE = exE[i2][hh];
            if(wI!=0.f || wE!=0.f){
                float hv = g_h[(size_t)ssrc[i2]*Cc + tid];
                accI += wI*hv;
                accE += wE*hv;
            }
        }
        __syncthreads();
    }

    float rdI = warp_sum(dI), rdE = warp_sum(dE);
    if(lane==0){ wred[wid][0]=rdI; wred[wid][1]=rdE; }
    __syncthreads();
    if(tid<4){
        float selfe = expf(aself[tid]-shmaxI[tid]);
        shdenI[tid] = wred[2*tid][0]+wred[2*tid+1][0]+selfe;
        shdenE[tid] = wred[2*tid][1]+wred[2*tid+1][1];
    }
    __syncthreads();

    float selfe = expf(aself[hh]-mymaxI);
    accI += selfe * g_h[(size_t)n*Cc + tid];

    float outI = accI/(shdenI[hh]+1e-9f);
    float outE = accE/(shdenE[hh]+1e-9f);
    g_x[(size_t)n*Cc + tid] = 0.5f*outI + 0.5f*outE;
}

// ---------------- host launch ----------------
#define GEMM_SMEM 65536

extern "C" void kernel_launch(void* const* d_in, const int* in_sizes, int n_in,
                              void* d_out, int out_size)
{
    const float* sent_emb  = (const float*)d_in[0];
    const float* proj_in_W = (const float*)d_in[1];
    const float* proj_in_b = (const float*)d_in[2];
    const float* proj_W    = (const float*)d_in[3];
    const float* proj_b    = (const float*)d_in[4];
    const float* asi       = (const float*)d_in[5];
    const float* adi       = (const float*)d_in[6];
    const float* ase       = (const float*)d_in[7];
    const float* ade       = (const float*)d_in[8];
    const float* mlp_W1    = (const float*)d_in[9];
    const float* mlp_b1    = (const float*)d_in[10];
    const float* mlp_W2    = (const float*)d_in[11];
    const float* mlp_b2    = (const float*)d_in[12];
    const int*   ev_sent   = (const int*)d_in[13];
    const int*   ev_start  = (const int*)d_in[14];
    const int*   ev_end    = (const int*)d_in[15];
    const int*   pair_idx  = (const int*)d_in[16];
    const int*   rel_type  = (const int*)d_in[17];
    const int*   target    = (const int*)d_in[18];
    float* out = (float*)d_out;

    static float *pE=nullptr,*pX=nullptr,*pA=nullptr,*pB=nullptr,*pU=nullptr,*pV=nullptr,*pH=nullptr;
    static __nv_bfloat16 *qE,*qX,*qWin,*qW1a,*qW1b,*qW1d,*qPrj;
    if(!pE){
        cudaGetSymbolAddress((void**)&pE, g_eemb);
        cudaGetSymbolAddress((void**)&pX, g_x);
        cudaGetSymbolAddress((void**)&pA, g_A);
        cudaGetSymbolAddress((void**)&pB, g_B);
        cudaGetSymbolAddress((void**)&pU, g_U);
        cudaGetSymbolAddress((void**)&pV, g_V);
        cudaGetSymbolAddress((void**)&pH, g_h);
        cudaGetSymbolAddress((void**)&qE,  g_PE);
        cudaGetSymbolAddress((void**)&qX,  g_PX);
        cudaGetSymbolAddress((void**)&qWin,g_PWin);
        cudaGetSymbolAddress((void**)&qW1a,g_PW1a);
        cudaGetSymbolAddress((void**)&qW1b,g_PW1b);
        cudaGetSymbolAddress((void**)&qW1d,g_PW1d);
        cudaGetSymbolAddress((void**)&qPrj,g_PPrj);
        cudaFuncSetAttribute(gemm_bf16, cudaFuncAttributeMaxDynamicSharedMemorySize, GEMM_SMEM);
    }

    // CSR build
    zero_counts<<<(Nn+255)/256,256>>>();
    count_edges<<<NE/256,256>>>(pair_idx);
    scan_counts<<<1,1024>>>();
    scatter_edges<<<NE/256,256>>>(pair_idx, rel_type);

    // event embeddings
    eemb_kernel<<<Nn,256>>>(sent_emb, ev_sent, ev_start, ev_end);

    // weight panels (hi/lo, pre-swizzled)
    prep_w<<<(Ee*Cc)/256,256>>>(proj_in_W, qWin, Cc, KC_E);
    prep_w<<<(Ee*MLPH)/256,256>>>(mlp_W1, qW1a, MLPH, KC_E);
    prep_w<<<(Ee*MLPH)/256,256>>>(mlp_W1 + (size_t)Ee*MLPH, qW1b, MLPH, KC_E);
    prep_w<<<(Cc*MLPH)/256,256>>>(mlp_W1 + (size_t)2*Ee*MLPH, qW1d, MLPH, KC_C);
    prep_w<<<(Cc*Cc)/256,256>>>(proj_W, qPrj, Cc, KC_C);

    // activation panels from e_emb
    prep_act<<<(Nn*Ee)/256,256>>>(pE, qE, Ee, KC_E);

    // x = e_emb @ Win + b ; A = e_emb @ W1a ; B = e_emb @ W1b
    gemm_bf16<<<dim3(Cc/128, Nn/128),256,GEMM_SMEM>>>(qE, qWin, KC_E, 0, proj_in_b, pX, nullptr,nullptr,nullptr, Cc);
    gemm_bf16<<<dim3(MLPH/128, Nn/128),256,GEMM_SMEM>>>(qE, qW1a, KC_E, 0, nullptr, pA, nullptr,nullptr,nullptr, MLPH);
    gemm_bf16<<<dim3(MLPH/128, Nn/128),256,GEMM_SMEM>>>(qE, qW1b, KC_E, 0, nullptr, pB, nullptr,nullptr,nullptr, MLPH);

    for(int it=0; it<3; it++){
        prep_act<<<(Nn*Cc)/256,256>>>(pX, qX, Cc, KC_C);
        // U = A + x@W1d + b1 ; V = B - x@W1d
        gemm_bf16<<<dim3(MLPH/128, Nn/128),256,GEMM_SMEM>>>(qX, qW1d, KC_C, 1, mlp_b1, pU, pA, pB, pV, MLPH);
        pair_kernel<<<Pp/8,256>>>(pair_idx, mlp_W2, mlp_b2, target,
                                  1.0f/(float)(it+1), it>0,
                                  (it==2) ? (out+1) : nullptr);
        if(it<2){
            gemm_bf16<<<dim3(Cc/128, Nn/128),256,GEMM_SMEM>>>(qX, qPrj, KC_C, 0, proj_b, pH, nullptr,nullptr,nullptr, Cc);
            s_kernel<<<Nn,128>>>(asi, adi, ase, ade);
            attn_kernel<<<Nn,256>>>();
        }
    }
    loss_reduce<<<1,256>>>(out);
}

// round 4
// speedup vs baseline: 1.9057x; 1.1664x over previous
#include <cuda_runtime.h>
#include <cuda_bf16.h>
#include <math.h>
#include <stdint.h>

#define Nn 4096
#define Pp 32768
#define Ee 768
#define Cc 256
#define Hh 4
#define Dd 64
#define Ll 256
#define Mm 8
#define MLPH 1024
#define NE (2*Pp)

// K chunks: K=768 -> 12 base chunks of 64 bf16; K=256 -> 4
#define KC_E 12
#define KC_C 4

// ---------------- scratch ----------------
__device__ float g_eemb[Nn*Ee];
__device__ float g_A[Nn*MLPH];
__device__ float g_B[Nn*MLPH];
__device__ float g_U[Nn*MLPH];
__device__ float g_V[Nn*MLPH];
__device__ float g_h[Nn*Cc];
__device__ float g_sis[Nn*Hh], g_sid[Nn*Hh], g_ses[Nn*Hh], g_sed[Nn*Hh];
__device__ unsigned char g_m1[Pp], g_m2[Pp];
__device__ float g_loss[Pp];
__device__ int g_cnt[Nn];
__device__ int g_rp[Nn+1];
__device__ int g_cur[Nn];
__device__ int g_esrc[NE];
__device__ unsigned int g_emeta[NE];

// bf16 pre-swizzled panels (tile = 128 rows x 64 bf16 = 8192 elems = 16KB)
__device__ __nv_bfloat16 g_PE  [(size_t)32*(2*KC_E)*8192];  // e_emb hi|lo (A panels)
__device__ __nv_bfloat16 g_PX  [(size_t)32*(2*KC_C)*8192];  // x hi|lo (A panels)
__device__ __nv_bfloat16 g_Wbig [(size_t)18*(2*KC_E)*8192]; // Win | W1a | W1b (B panels)
__device__ __nv_bfloat16 g_Wloop[(size_t)10*(2*KC_C)*8192]; // W1d | proj_W (B panels)

__device__ __forceinline__ float warp_sum(float v){
#pragma unroll
    for(int o=16;o;o>>=1) v+=__shfl_xor_sync(0xffffffffu,v,o);
    return v;
}

// ---------------- PTX helpers ----------------
__device__ __forceinline__ uint32_t smem_to_u32(const void* p){
    uint32_t a;
    asm("{ .reg .u64 t; cvta.to.shared.u64 t, %1; cvt.u32.u64 %0, t; }" : "=r"(a) : "l"(p));
    return a;
}
__device__ __forceinline__ void ldmx4(uint32_t &r0,uint32_t &r1,uint32_t &r2,uint32_t &r3,uint32_t addr){
    asm volatile("ldmatrix.sync.aligned.m8n8.x4.shared.b16 {%0,%1,%2,%3}, [%4];"
        : "=r"(r0),"=r"(r1),"=r"(r2),"=r"(r3) : "r"(addr));
}
__device__ __forceinline__ void mma16816(float* c, const uint32_t* a, uint32_t b0, uint32_t b1){
    asm volatile("mma.sync.aligned.m16n8k16.row.col.f32.bf16.bf16.f32 "
        "{%0,%1,%2,%3}, {%4,%5,%6,%7}, {%8,%9}, {%0,%1,%2,%3};"
        : "+f"(c[0]),"+f"(c[1]),"+f"(c[2]),"+f"(c[3])
        : "r"(a[0]),"r"(a[1]),"r"(a[2]),"r"(a[3]),"r"(b0),"r"(b1));
}
#define CP_ASYNC16(dst,src) \
    asm volatile("cp.async.cg.shared.global [%0], [%1], 16;" :: "r"(dst),"l"(src))
#define CP_COMMIT asm volatile("cp.async.commit_group;" ::: "memory")
#define CP_WAIT1  asm volatile("cp.async.wait_group 1;" ::: "memory")
#define CP_WAIT0  asm volatile("cp.async.wait_group 0;" ::: "memory")

__device__ __forceinline__ uint32_t sw128(uint32_t off){ return off ^ ((off>>3)&0x70u); }

// write one fp32 value as hi/lo bf16 into a pre-swizzled panel image
__device__ __forceinline__ void panel_write(__nv_bfloat16* pan, int panKc, int mglob, int cglob, float v){
    int pm = mglob>>7, prow = mglob&127, chunk = cglob>>6, col = cglob&63;
    uint32_t off = sw128((uint32_t)(prow*128 + col*2));
    char* hi = (char*)(pan + ((size_t)pm*(2*panKc)+chunk)*8192);
    char* lo = (char*)(pan + ((size_t)pm*(2*panKc)+panKc+chunk)*8192);
    __nv_bfloat16 h = __float2bfloat16(v);
    *(__nv_bfloat16*)(hi+off) = h;
    *(__nv_bfloat16*)(lo+off) = __float2bfloat16(v - __bfloat162float(h));
}

// ---------------- CSR build ----------------
__global__ void zero_counts(){
    int i = blockIdx.x*256 + threadIdx.x;
    if(i<Nn) g_cnt[i]=0;
}
__global__ void count_edges(const int* __restrict__ pair_idx){
    int e = blockIdx.x*256 + threadIdx.x;
    if(e>=NE) return;
    int p = e & (Pp-1);
    int dst = (e<Pp) ? pair_idx[2*p+1] : pair_idx[2*p];
    atomicAdd(&g_cnt[dst],1);
}
__global__ void scan_counts(){
    __shared__ int sh[1024];
    int tid=threadIdx.x;
    int b = tid*4;
    int c0=g_cnt[b], c1=g_cnt[b+1], c2=g_cnt[b+2], c3=g_cnt[b+3];
    int tot=c0+c1+c2+c3;
    sh[tid]=tot; __syncthreads();
    for(int off=1;off<1024;off<<=1){
        int add = (tid>=off)? sh[tid-off] : 0;
        __syncthreads();
        sh[tid]+=add;
        __syncthreads();
    }
    int excl = sh[tid]-tot;
    g_rp[b]=excl;            g_cur[b]=excl;
    g_rp[b+1]=excl+c0;       g_cur[b+1]=excl+c0;
    g_rp[b+2]=excl+c0+c1;    g_cur[b+2]=excl+c0+c1;
    g_rp[b+3]=excl+c0+c1+c2; g_cur[b+3]=excl+c0+c1+c2;
    if(tid==1023) g_rp[Nn]=excl+tot;
}
__global__ void scatter_edges(const int* __restrict__ pair_idx, const int* __restrict__ rel_type){
    int e = blockIdx.x*256 + threadIdx.x;
    if(e>=NE) return;
    int p = e & (Pp-1);
    int half = (e>=Pp);
    int src = half ? pair_idx[2*p+1] : pair_idx[2*p];
    int dst = half ? pair_idx[2*p]   : pair_idx[2*p+1];
    unsigned int intra = (rel_type[p]==0) ? 0x40000000u : 0u;
    int slot = atomicAdd(&g_cur[dst],1);
    g_esrc[slot]=src;
    g_emeta[slot] = (unsigned int)p | (half ? 0x80000000u : 0u) | intra;
}

// ---------------- event embedding gather-mean ----------------
__global__ void eemb_kernel(const float* __restrict__ sent_emb,
                            const int* __restrict__ ev_sent,
                            const int* __restrict__ ev_start,
                            const int* __restrict__ ev_end){
    int n = blockIdx.x;
    int tid = threadIdx.x; // 256
    int s = ev_sent[n], st = ev_start[n], en = ev_end[n];
    float inv = 1.0f/(float)(en-st);
    const float* base = sent_emb + (size_t)s*Ll*Ee;
    for(int c=tid;c<Ee;c+=256){
        float acc=0.f;
#pragma unroll
        for(int m=0;m<Mm;m++){
            int pos = st+m;
            if(pos<en){
                int pc = pos<Ll-1?pos:Ll-1;
                acc += base[(size_t)pc*Ee + c];
            }
        }
        g_eemb[(size_t)n*Ee+c]=acc*inv;
    }
}

// ---------------- panel prep ----------------
__global__ void prep_act(const float* __restrict__ X, __nv_bfloat16* __restrict__ P, int K, int KcN){
    int idx = blockIdx.x*256 + threadIdx.x;
    int m = idx / K, k = idx - m*K;
    float v = X[idx];
    panel_write(P, KcN, m, k, v);
}
__global__ void prep_w(const float* __restrict__ W, __nv_bfloat16* __restrict__ P, int N, int KcN){
    int idx = blockIdx.x*256 + threadIdx.x;
    int k = idx / N, n = idx - k*N;
    float v = W[idx];
    __nv_bfloat16 hi = __float2bfloat16(v);
    __nv_bfloat16 lo = __float2bfloat16(v - __bfloat162float(hi));
    int nblk = n>>7, row = n&127, chunk = k>>6, col = k&63;
    uint32_t off = sw128((uint32_t)(row*128 + col*2));
    char* baseHi = (char*)(P + ((size_t)nblk*(2*KcN)+chunk)*8192);
    char* baseLo = (char*)(P + ((size_t)nblk*(2*KcN)+KcN+chunk)*8192);
    *(__nv_bfloat16*)(baseHi + off) = hi;
    *(__nv_bfloat16*)(baseLo + off) = lo;
}

// ---------------- fused mma.sync bf16-split GEMM ----------------
// Epilogue types: 0 = fp32 out (+bias); 1 = UV (U=addA+g+bias, V=addB-g); 2 = panel hi/lo out (+bias)
struct Epi {
    int type;
    float* out;
    const float* bias;
    int N;                 // output row stride (type 0/1)
    float* out2;           // V (type 1)
    __nv_bfloat16* pan;    // panel (type 2)
    int panKc;
};

__global__ void __launch_bounds__(256,2)
gemm_fused(const __nv_bfloat16* __restrict__ Apan,
           const __nv_bfloat16* __restrict__ Bpan,
           int KcN, int s1, int s2,
           Epi e0, Epi e1, Epi e2,
           const float* __restrict__ addA,
           const float* __restrict__ addB)
{
    extern __shared__ __align__(128) char smem[];
    const uint32_t sb = smem_to_u32(smem);
    const int tid = threadIdx.x;
    const int wid = tid >> 5;
    const int lane = tid & 31;
    const int mblk = blockIdx.y, nblk = blockIdx.x;
    const int wm = wid & 3;
    const int wn = wid >> 2;
    const int nc = 3*KcN;

    float acc[2][8][4];
#pragma unroll
    for(int i=0;i<2;i++)
#pragma unroll
        for(int j=0;j<8;j++)
#pragma unroll
            for(int q=0;q<4;q++) acc[i][j][q]=0.f;

    const int arow = wm*32 + (lane & 15);
    const int acol = ((lane >> 4) & 1) * 8;
    const int bnof = ((lane >> 4) & 1) * 8 + (lane & 7);
    const int bkof = ((lane >> 3) & 1) * 8;

    auto chunk_src = [&](int c, const uint4*& Ag, const uint4*& Bg){
        int seg = (c >= 2*KcN) ? 2 : ((c >= KcN) ? 1 : 0);
        int within = c - seg*KcN;
        int aC = (seg==1 ? KcN : 0) + within;
        int bC = (seg==2 ? KcN : 0) + within;
        Ag = (const uint4*)(Apan + ((size_t)mblk*(2*KcN)+aC)*8192);
        Bg = (const uint4*)(Bpan + ((size_t)nblk*(2*KcN)+bC)*8192);
    };

    {
        const uint4 *Ag, *Bg;
        chunk_src(0, Ag, Bg);
#pragma unroll
        for(int i=0;i<4;i++){
            CP_ASYNC16(sb + (tid + i*256)*16, Ag + tid + i*256);
            CP_ASYNC16(sb + 16384 + (tid + i*256)*16, Bg + tid + i*256);
        }
        CP_COMMIT;
    }

    for(int c=0;c<nc;c++){
        int buf = c & 1;
        if(c+1 < nc){
            const uint4 *Ag, *Bg;
            chunk_src(c+1, Ag, Bg);
            uint32_t db = sb + ((c+1)&1)*32768;
#pragma unroll
            for(int i=0;i<4;i++){
                CP_ASYNC16(db + (tid + i*256)*16, Ag + tid + i*256);
                CP_ASYNC16(db + 16384 + (tid + i*256)*16, Bg + tid + i*256);
            }
            CP_COMMIT;
            CP_WAIT1;
        } else {
            CP_WAIT0;
        }
        __syncthreads();

        uint32_t abase = sb + buf*32768;
        uint32_t bbase = abase + 16384;
#pragma unroll
        for(int ks=0;ks<4;ks++){
            uint32_t af[2][4];
#pragma unroll
            for(int mf=0;mf<2;mf++){
                uint32_t off = (uint32_t)((arow + mf*16)*128 + (ks*16 + acol)*2);
                ldmx4(af[mf][0],af[mf][1],af[mf][2],af[mf][3], abase + sw128(off));
            }
#pragma unroll
            for(int g=0;g<4;g++){
                uint32_t b0,b1,b2,b3;
                uint32_t off = (uint32_t)((wn*64 + g*16 + bnof)*128 + (ks*16 + bkof)*2);
                ldmx4(b0,b1,b2,b3, bbase + sw128(off));
#pragma unroll
                for(int mf=0;mf<2;mf++){
                    mma16816(acc[mf][2*g+0], af[mf], b0, b1);
                    mma16816(acc[mf][2*g+1], af[mf], b2, b3);
                }
            }
        }
        __syncthreads();
    }

    // select epilogue region
    Epi E; int regStart;
    if(nblk < s1){ E = e0; regStart = 0; }
    else if(nblk < s2){ E = e1; regStart = s1; }
    else { E = e2; regStart = s2; }

    int rbase = mblk*128 + wm*32 + (lane>>2);
    int cbase = (nblk - regStart)*128 + wn*64 + (lane&3)*2;

#pragma unroll
    for(int mf=0;mf<2;mf++){
#pragma unroll
        for(int nf=0;nf<8;nf++){
            int r  = rbase + mf*16;
            int cc = cbase + nf*8;
            float g0=acc[mf][nf][0], g1=acc[mf][nf][1];
            float g2=acc[mf][nf][2], g3=acc[mf][nf][3];
            if(E.type==0){
                float b0 = E.bias ? E.bias[cc]   : 0.f;
                float b1 = E.bias ? E.bias[cc+1] : 0.f;
                size_t i0 = (size_t)r*E.N + cc;
                size_t i1 = (size_t)(r+8)*E.N + cc;
                *(float2*)(E.out + i0) = make_float2(g0+b0, g1+b1);
                *(float2*)(E.out + i1) = make_float2(g2+b0, g3+b1);
            } else if(E.type==1){
                float b0 = E.bias[cc], b1 = E.bias[cc+1];
                size_t i0 = (size_t)r*E.N + cc;
                size_t i1 = (size_t)(r+8)*E.N + cc;
                float2 a0 = *(const float2*)(addA + i0);
                float2 a1 = *(const float2*)(addA + i1);
                float2 v0 = *(const float2*)(addB + i0);
                float2 v1 = *(const float2*)(addB + i1);
                *(float2*)(E.out  + i0) = make_float2(a0.x+g0+b0, a0.y+g1+b1);
                *(float2*)(E.out  + i1) = make_float2(a1.x+g2+b0, a1.y+g3+b1);
                *(float2*)(E.out2 + i0) = make_float2(v0.x-g0, v0.y-g1);
                *(float2*)(E.out2 + i1) = make_float2(v1.x-g2, v1.y-g3);
            } else {
                float b0 = E.bias ? E.bias[cc]   : 0.f;
                float b1 = E.bias ? E.bias[cc+1] : 0.f;
                panel_write(E.pan, E.panKc, r,   cc,   g0+b0);
                panel_write(E.pan, E.panKc, r,   cc+1, g1+b1);
                panel_write(E.pan, E.panKc, r+8, cc,   g2+b0);
                panel_write(E.pan, E.panKc, r+8, cc+1, g3+b1);
            }
        }
    }
}

// ---------------- pair MLP + softmax + loss + masks ----------------
__global__ void pair_kernel(const int* __restrict__ pair_idx,
                            const float* __restrict__ W2, const float* __restrict__ b2,
                            const int* __restrict__ target,
                            float w_it, int accum, float* __restrict__ pred_out)
{
    __shared__ float W2s[3072];
    __shared__ float b2s[3];
    int tid = threadIdx.x; // 256
    for(int i=tid;i<3072;i+=256) W2s[i]=W2[i];
    if(tid<3) b2s[tid]=b2[tid];
    __syncthreads();
    int p = blockIdx.x*8 + (tid>>5);
    int lane = tid & 31;
    int p0 = pair_idx[2*p], p1 = pair_idx[2*p+1];
    const float* ur = g_U + (size_t)p0*MLPH;
    const float* vr = g_V + (size_t)p1*MLPH;
    float a0=0.f,a1=0.f,a2=0.f;
#pragma unroll 4
    for(int j=lane;j<MLPH;j+=32){
        float hv = ur[j]+vr[j];
        hv = fmaxf(hv,0.f);
        a0 += hv*W2s[j*3+0];
        a1 += hv*W2s[j*3+1];
        a2 += hv*W2s[j*3+2];
    }
    a0=warp_sum(a0); a1=warp_sum(a1); a2=warp_sum(a2);
    if(lane==0){
        float r0=a0+b2s[0], r1=a1+b2s[1], r2=a2+b2s[2];
        float mv=r0; int arg=0;
        if(r1>mv){mv=r1;arg=1;}
        if(r2>mv){mv=r2;arg=2;}
        float e0=expf(r0-mv), e1=expf(r1-mv), e2=expf(r2-mv);
        float ssum=e0+e1+e2;
        int conf = (1.0f/ssum) > 0.5f;
        g_m1[p] = (unsigned char)(conf && (arg==1));
        g_m2[p] = (unsigned char)(conf && (arg==2));
        int t = target[p];
        float lse = mv + logf(ssum);
        float pr = (t==0)?r0:((t==1)?r1:r2);
        float prev = accum ? g_loss[p] : 0.f;
        g_loss[p] = prev + w_it*(lse - pr);
        if(pred_out){
            pred_out[3*p+0]=r0; pred_out[3*p+1]=r1; pred_out[3*p+2]=r2;
        }
    }
}

__global__ void loss_reduce(float* __restrict__ out){
    __shared__ float sh[256];
    int tid = threadIdx.x;
    float s=0.f;
    for(int i=tid;i<Pp;i+=256) s+=g_loss[i];
    sh[tid]=s; __syncthreads();
    for(int o=128;o;o>>=1){
        if(tid<o) sh[tid]+=sh[tid+o];
        __syncthreads();
    }
    if(tid==0) out[0]=sh[0]/(float)Pp;
}

// ---------------- per-node attention score precompute ----------------
__global__ void s_kernel(const float* __restrict__ asi, const float* __restrict__ adi,
                         const float* __restrict__ ase, const float* __restrict__ ade){
    int n = blockIdx.x;
    int w = threadIdx.x>>5, lane = threadIdx.x&31;
    const float* hr = g_h + (size_t)n*Cc + w*Dd;
    float h0 = hr[lane], h1 = hr[32+lane];
    float v0 = h0*asi[w*Dd+lane] + h1*asi[w*Dd+32+lane];
    float v1 = h0*adi[w*Dd+lane] + h1*adi[w*Dd+32+lane];
    float v2 = h0*ase[w*Dd+lane] + h1*ase[w*Dd+32+lane];
    float v3 = h0*ade[w*Dd+lane] + h1*ade[w*Dd+32+lane];
    v0=warp_sum(v0); v1=warp_sum(v1); v2=warp_sum(v2); v3=warp_sum(v3);
    if(lane==0){
        g_sis[n*Hh+w]=v0; g_sid[n*Hh+w]=v1;
        g_ses[n*Hh+w]=v2; g_sed[n*Hh+w]=v3;
    }
}

// ---------------- fused GAT attention, writes x panels directly ----------------
__global__ void attn_kernel(){
    int n = blockIdx.x;
    int tid = threadIdx.x; // 256
    int hh = tid>>6;
    __shared__ int ssrc[64];
    __shared__ unsigned int smeta[64];
    __shared__ float exI[64][4];
    __shared__ float exE[64][4];
    __shared__ float shmaxI[4], shmaxE[4], shdenI[4], shdenE[4];
    __shared__ float wred[8][8];

    float sdI[4], sdE[4], aself[4];
#pragma unroll
    for(int h=0;h<4;h++){
        sdI[h]=g_sid[n*4+h];
        sdE[h]=g_sed[n*4+h];
        float a = g_sis[n*4+h]+sdI[h];
        aself[h] = (a>=0.f)? a : 0.2f*a;
    }

    int beg = g_rp[n], end = g_rp[n+1];

    float mI[4], mE[4];
#pragma unroll
    for(int h=0;h<4;h++){ mI[h]=fmaxf(-1e9f,aself[h]); mE[h]=-1e9f; }
    for(int e=beg+tid;e<end;e+=256){
        int src = g_esrc[e];
        unsigned int meta = g_emeta[e];
        unsigned int p = meta & 0x0FFFFFFFu;
        bool mm = (meta & 0x80000000u) ? (g_m2[p]!=0) : (g_m1[p]!=0);
        if(!mm) continue;
        if(meta & 0x40000000u){
#pragma unroll
            for(int h=0;h<4;h++){
                float a = g_sis[src*4+h]+sdI[h];
                a = (a>=0.f)? a : 0.2f*a;
                mI[h]=fmaxf(mI[h],a);
            }
        } else {
#pragma unroll
            for(int h=0;h<4;h++){
                float a = g_ses[src*4+h]+sdE[h];
                a = (a>=0.f)? a : 0.2f*a;
                mE[h]=fmaxf(mE[h],a);
            }
        }
    }
#pragma unroll
    for(int o=16;o;o>>=1){
#pragma unroll
        for(int h=0;h<4;h++){
            mI[h]=fmaxf(mI[h],__shfl_xor_sync(0xffffffffu,mI[h],o));
            mE[h]=fmaxf(mE[h],__shfl_xor_sync(0xffffffffu,mE[h],o));
        }
    }
    int wid = tid>>5, lane = tid&31;
    if(lane==0){
#pragma unroll
        for(int h=0;h<4;h++){ wred[wid][h]=mI[h]; wred[wid][4+h]=mE[h]; }
    }
    __syncthreads();
    if(tid<8){
        float m=-1e9f;
#pragma unroll
        for(int w=0;w<8;w++) m=fmaxf(m,wred[w][tid]);
        if(tid<4) shmaxI[tid]=m; else shmaxE[tid-4]=m;
    }
    __syncthreads();
    float mymaxI = shmaxI[hh];
    float mymaxE = shmaxE[hh];

    float accI=0.f, accE=0.f, dI=0.f, dE=0.f;
    for(int c0=beg;c0<end;c0+=64){
        int ne = min(64, end-c0);
        if(tid<ne){ ssrc[tid]=g_esrc[c0+tid]; smeta[tid]=g_emeta[c0+tid]; }
        __syncthreads();
        int i = tid & 63;
        if(i<ne){
            int src = ssrc[i];
            unsigned int meta = smeta[i];
            unsigned int p = meta & 0x0FFFFFFFu;
            bool mm = (meta & 0x80000000u) ? (g_m2[p]!=0) : (g_m1[p]!=0);
            float eI=0.f, eE=0.f;
            if(mm){
                if(meta & 0x40000000u){
                    float a = g_sis[src*4+hh]+sdI[hh];
                    a = (a>=0.f)? a : 0.2f*a;
                    eI = expf(a - mymaxI);
                } else {
                    float a = g_ses[src*4+hh]+sdE[hh];
                    a = (a>=0.f)? a : 0.2f*a;
                    eE = expf(a - mymaxE);
                }
            }
            exI[i][hh]=eI; exE[i][hh]=eE;
            dI += eI; dE += eE;
        }
        __syncthreads();
        for(int i2=0;i2<ne;i2++){
            float wI = exI[i2][hh];
            float wE = exE[i2][hh];
            if(wI!=0.f || wE!=0.f){
                float hv = g_h[(size_t)ssrc[i2]*Cc + tid];
                accI += wI*hv;
                accE += wE*hv;
            }
        }
        __syncthreads();
    }

    float rdI = warp_sum(dI), rdE = warp_sum(dE);
    if(lane==0){ wred[wid][0]=rdI; wred[wid][1]=rdE; }
    __syncthreads();
    if(tid<4){
        float selfe = expf(aself[tid]-shmaxI[tid]);
        shdenI[tid] = wred[2*tid][0]+wred[2*tid+1][0]+selfe;
        shdenE[tid] = wred[2*tid][1]+wred[2*tid+1][1];
    }
    __syncthreads();

    float selfe = expf(aself[hh]-mymaxI);
    accI += selfe * g_h[(size_t)n*Cc + tid];

    float outI = accI/(shdenI[hh]+1e-9f);
    float outE = accE/(shdenE[hh]+1e-9f);
    float val = 0.5f*outI + 0.5f*outE;
    panel_write(g_PX, KC_C, n, tid, val);   // x consumed only through panels
}

// ---------------- host launch ----------------
#define GEMM_SMEM 65536

extern "C" void kernel_launch(void* const* d_in, const int* in_sizes, int n_in,
                              void* d_out, int out_size)
{
    const float* sent_emb  = (const float*)d_in[0];
    const float* proj_in_W = (const float*)d_in[1];
    const float* proj_in_b = (const float*)d_in[2];
    const float* proj_W    = (const float*)d_in[3];
    const float* proj_b    = (const float*)d_in[4];
    const float* asi       = (const float*)d_in[5];
    const float* adi       = (const float*)d_in[6];
    const float* ase       = (const float*)d_in[7];
    const float* ade       = (const float*)d_in[8];
    const float* mlp_W1    = (const float*)d_in[9];
    const float* mlp_b1    = (const float*)d_in[10];
    const float* mlp_W2    = (const float*)d_in[11];
    const float* mlp_b2    = (const float*)d_in[12];
    const int*   ev_sent   = (const int*)d_in[13];
    const int*   ev_start  = (const int*)d_in[14];
    const int*   ev_end    = (const int*)d_in[15];
    const int*   pair_idx  = (const int*)d_in[16];
    const int*   rel_type  = (const int*)d_in[17];
    const int*   target    = (const int*)d_in[18];
    float* out = (float*)d_out;

    static float *pE=nullptr,*pA=nullptr,*pB=nullptr,*pU=nullptr,*pV=nullptr,*pH=nullptr;
    static __nv_bfloat16 *qE,*qX,*qWbig,*qWloop;
    if(!pE){
        cudaGetSymbolAddress((void**)&pE, g_eemb);
        cudaGetSymbolAddress((void**)&pA, g_A);
        cudaGetSymbolAddress((void**)&pB, g_B);
        cudaGetSymbolAddress((void**)&pU, g_U);
        cudaGetSymbolAddress((void**)&pV, g_V);
        cudaGetSymbolAddress((void**)&pH, g_h);
        cudaGetSymbolAddress((void**)&qE,    g_PE);
        cudaGetSymbolAddress((void**)&qX,    g_PX);
        cudaGetSymbolAddress((void**)&qWbig, g_Wbig);
        cudaGetSymbolAddress((void**)&qWloop,g_Wloop);
        cudaFuncSetAttribute(gemm_fused, cudaFuncAttributeMaxDynamicSharedMemorySize, GEMM_SMEM);
    }

    // CSR build
    zero_counts<<<(Nn+255)/256,256>>>();
    count_edges<<<NE/256,256>>>(pair_idx);
    scan_counts<<<1,1024>>>();
    scatter_edges<<<NE/256,256>>>(pair_idx, rel_type);

    // event embeddings
    eemb_kernel<<<Nn,256>>>(sent_emb, ev_sent, ev_start, ev_end);

    // weight panels: Wbig = [Win(2) | W1a(8) | W1b(8)] nblks, KC_E
    prep_w<<<(Ee*Cc)/256,256>>>(proj_in_W, qWbig, Cc, KC_E);
    prep_w<<<(Ee*MLPH)/256,256>>>(mlp_W1, qWbig + (size_t)2*(2*KC_E)*8192, MLPH, KC_E);
    prep_w<<<(Ee*MLPH)/256,256>>>(mlp_W1 + (size_t)Ee*MLPH, qWbig + (size_t)10*(2*KC_E)*8192, MLPH, KC_E);
    // Wloop = [W1d(8) | proj_W(2)] nblks, KC_C
    prep_w<<<(Cc*MLPH)/256,256>>>(mlp_W1 + (size_t)2*Ee*MLPH, qWloop, MLPH, KC_C);
    prep_w<<<(Cc*Cc)/256,256>>>(proj_W, qWloop + (size_t)8*(2*KC_C)*8192, Cc, KC_C);

    // activation panels from e_emb
    prep_act<<<(Nn*Ee)/256,256>>>(pE, qE, Ee, KC_E);

    // fused big GEMM: [x-panels | A | B] = e_emb @ [Win | W1a | W1b]
    {
        Epi ex;  ex.type=2;  ex.out=nullptr; ex.bias=proj_in_b; ex.N=0;    ex.out2=nullptr; ex.pan=qX; ex.panKc=KC_C;
        Epi ea;  ea.type=0;  ea.out=pA;      ea.bias=nullptr;   ea.N=MLPH; ea.out2=nullptr; ea.pan=nullptr; ea.panKc=0;
        Epi eb;  eb.type=0;  eb.out=pB;      eb.bias=nullptr;   eb.N=MLPH; eb.out2=nullptr; eb.pan=nullptr; eb.panKc=0;
        gemm_fused<<<dim3(18, Nn/128),256,GEMM_SMEM>>>(qE, qWbig, KC_E, 2, 10, ex, ea, eb, nullptr, nullptr);
    }

    for(int it=0; it<3; it++){
        // fused loop GEMM: [U/V | h] = x @ [W1d | proj_W]   (h skipped on last iter)
        Epi eu;  eu.type=1;  eu.out=pU;  eu.bias=mlp_b1; eu.N=MLPH; eu.out2=pV;      eu.pan=nullptr; eu.panKc=0;
        Epi eh;  eh.type=0;  eh.out=pH;  eh.bias=proj_b; eh.N=Cc;   eh.out2=nullptr; eh.pan=nullptr; eh.panKc=0;
        int gx = (it<2) ? 10 : 8;
        gemm_fused<<<dim3(gx, Nn/128),256,GEMM_SMEM>>>(qX, qWloop, KC_C, 8, 10, eu, eh, eh, pA, pB);

        pair_kernel<<<Pp/8,256>>>(pair_idx, mlp_W2, mlp_b2, target,
                                  1.0f/(float)(it+1), it>0,
                                  (it==2) ? (out+1) : nullptr);
        if(it<2){
            s_kernel<<<Nn,128>>>(asi, adi, ase, ade);
            attn_kernel<<<Nn,256>>>();
        }
    }
    loss_reduce<<<1,256>>>(out);
}